// round 13
// baseline (speedup 1.0000x reference)
#include <cuda_runtime.h>

#define BB    32
#define CC    16
#define RES   128
#define NANG  64
#define NTILE (NANG * 32)

// Weighted image, batch-innermost: g_W[(y*128+x)*32 + b]
__device__ float  g_W[RES * RES * BB];
__device__ float2 g_trig[NANG];
__device__ int4   g_win[NTILE];        // per (angle,quad): jAw, jBw, jCw, jDw

// ---------------------------------------------------------------------------
// packed f32x2 helpers (sm_103a)
// ---------------------------------------------------------------------------
typedef unsigned long long u64;
__device__ __forceinline__ u64 pk2(float v) {
    u64 r; asm("mov.b64 %0,{%1,%1};" : "=l"(r) : "f"(v)); return r;
}
__device__ __forceinline__ u64 f2fma(u64 a, u64 b, u64 c) {
    u64 d; asm("fma.rn.f32x2 %0,%1,%2,%3;" : "=l"(d) : "l"(a), "l"(b), "l"(c)); return d;
}
__device__ __forceinline__ float2 up2(u64 v) {
    float2 f; asm("mov.b64 {%0,%1},%2;" : "=f"(f.x), "=f"(f.y) : "l"(v)); return f;
}

// ---------------------------------------------------------------------------
// Interval helper: intersect {j : lo < P + Q*j < hi} into [jmn, jmx].
// ---------------------------------------------------------------------------
__device__ __forceinline__ void isect(float P, float Q, float lo, float hi,
                                      float& jmn, float& jmx) {
    if (Q == 0.f) {
        if (P <= lo || P >= hi) { jmn = 1e9f; jmx = -1e9f; }
    } else {
        float t0 = (lo - P) / Q, t1 = (hi - P) / Q;
        jmn = fmaxf(jmn, fminf(t0, t1));
        jmx = fminf(jmx, fmaxf(t0, t1));
    }
}

// ---------------------------------------------------------------------------
// Kernel 1: channel-weighted image -> (y,x,b) layout; windows+trig in spare
// warp of blocks 0..63; bias-initializes out (later kernels accumulate).
// ---------------------------------------------------------------------------
__global__ __launch_bounds__(1024) void k_weight(const float* __restrict__ x,
                                                 const float* __restrict__ w,
                                                 const float* __restrict__ angles,
                                                 const float* __restrict__ bias,
                                                 float* __restrict__ out) {
    __shared__ float S[RES][33];
    const int y = blockIdx.x, tid = threadIdx.x;

    // ---- bias init of out (262144 elems; 128 blocks x 1024 x 2) ----
    {
        const float bv = __ldg(&bias[0]);
        const int g0 = y * 1024 + tid;
        out[g0] = bv;
        out[g0 + 131072] = bv;
    }

    // ---- window/trig precompute: warp 31 of blocks 0..63 ----
    if (y < NANG && tid >= 992) {
        const int a = y, quad = tid - 992;
        const float theta = __ldg(&angles[a]);
        const float c = cosf(theta), s = sinf(theta);
        if (quad == 0) g_trig[a] = make_float2(c, s);

        int jAw = 1 << 30, jBw = -(1 << 30), jCw = -(1 << 30), jDw = 1 << 30;
#pragma unroll 1
        for (int r = 0; r < 4; r++) {
            const int i = quad * 4 + r;
            const float ci = (float)i - 63.5f;
            const float ax = fmaf(ci, c, 63.5f);
            const float ay = fmaf(ci, s, 63.5f);
            const float A  = fmaf(63.5f, s, ax), Bq = -s;
            const float Cq = fmaf(-63.5f, c, ay), Dq = c;

            float jmn = 0.f, jmx = 127.f;
            isect(A, Bq, -1.f, 128.f, jmn, jmx);
            isect(Cq, Dq, -1.f, 128.f, jmn, jmx);
            jmn = fminf(fmaxf(jmn, 0.f), 127.f);
            jmx = fminf(fmaxf(jmx, 0.f), 127.f);
            int jA, jB;
            if (jmn > jmx) { jA = 0; jB = -1; }
            else { jA = max(0, (int)floorf(jmn) - 1); jB = min(127, (int)ceilf(jmx) + 1); }

            float jmn2 = 0.f, jmx2 = 127.f;
            isect(A, Bq, 0.01f, 126.99f, jmn2, jmx2);
            isect(Cq, Dq, 0.01f, 126.99f, jmn2, jmx2);
            jmn2 = fminf(fmaxf(jmn2, 0.f), 127.f);
            jmx2 = fminf(fmaxf(jmx2, 0.f), 127.f);
            int jC, jD;
            if (jmn2 > jmx2) { jC = jB + 1; jD = jB; }
            else {
                jC = max(jA, (int)ceilf(jmn2) + 1);
                jD = min(jB, (int)floorf(jmx2) - 1);
                if (jC > jD) { jC = jB + 1; jD = jB; }
            }
            jAw = min(jAw, jA); jBw = max(jBw, jB);
            jCw = max(jCw, jC); jDw = min(jDw, jD);
        }
        if (jDw < jCw - 1) jDw = jCw - 1;           // [jCw,jDw] may be empty
        g_win[a * 32 + quad] = make_int4(jAw, jBw, jCw, jDw);
    }

    // ---- weighted image: thread = (batch b, 4 x-positions), float4 reads ----
    float wv[CC];
#pragma unroll
    for (int c = 0; c < CC; c++) wv[c] = __ldg(&w[c]);

    const int xi4 = tid & 31;
    const int b   = tid >> 5;
    const float4* px = (const float4*)(x + ((size_t)(b * CC)) * RES * RES
                                         + (size_t)y * RES) + xi4;
    float4 acc = make_float4(0.f, 0.f, 0.f, 0.f);
#pragma unroll
    for (int c = 0; c < CC; c++) {
        float4 t = __ldg(px + (size_t)c * (RES * RES / 4));
        acc.x = fmaf(wv[c], t.x, acc.x);
        acc.y = fmaf(wv[c], t.y, acc.y);
        acc.z = fmaf(wv[c], t.z, acc.z);
        acc.w = fmaf(wv[c], t.w, acc.w);
    }
    S[4 * xi4 + 0][b] = acc.x;
    S[4 * xi4 + 1][b] = acc.y;
    S[4 * xi4 + 2][b] = acc.z;
    S[4 * xi4 + 3][b] = acc.w;
    __syncthreads();

    const int bb = tid & 31, xg = tid >> 5;
#pragma unroll
    for (int k = 0; k < 4; k++) {
        int x2 = xg + k * 32;
        g_W[(y * 128 + x2) * 32 + bb] = S[x2][bb];
    }
}

// ---------------------------------------------------------------------------
// Kernel 2: FAST interior only. Block = 128 = 4 warps = 4 segments of one
// tile's [jCw, jDw]. No masked lambda -> low regs -> high occupancy.
// Lanes: sub = lane>>3 (row in quad), q = lane&7 (batches 4q..4q+3).
// Partials accumulated into out via atomicAdd (bias pre-initialized).
// ---------------------------------------------------------------------------
__global__ __launch_bounds__(128) void k_fast(float* __restrict__ out) {
    const int lane = threadIdx.x & 31;
    const int seg  = threadIdx.x >> 5;              // 0..3
    const int sub  = lane >> 3;
    const int q    = lane & 7;
    const int bx   = blockIdx.x;
    const int quad = (bx & 1) ? (16 + (bx >> 1)) : (15 - (bx >> 1));
    const int i    = quad * 4 + sub;
    const int a    = blockIdx.y;

    const int4 wn = g_win[a * 32 + quad];
    const int lenF = wn.w - wn.z + 1;               // interior length
    if (lenF <= 0) return;

    const int f0 = wn.z + (seg * lenF) / 4;
    const int f1 = wn.z + ((seg + 1) * lenF) / 4 - 1;
    if (f0 > f1) return;

    const float2 cs = g_trig[a];
    const float c = cs.x, s = cs.y;
    const float ci = (float)i - 63.5f;
    const float ax = fmaf(ci, c, 63.5f);
    const float ay = fmaf(ci, s, 63.5f);

    u64 accA = 0, accB = 0, accC = 0, accD = 0;
    const ulonglong2* Wq = (const ulonglong2*)g_W + q;
    const u64 M1 = pk2(-1.f);

    float cj = (float)f0 - 63.5f;                   // exact; += 1.0f stays exact
#pragma unroll 4
    for (int j = f0; j <= f1; j++) {
        float xs = fmaf(-s, cj, ax);
        float ys = fmaf(c, cj, ay);
        cj += 1.0f;
        float fx = floorf(xs), fy = floorf(ys);
        float wx = xs - fx,    wy = ys - fy;
        int idx = __float2int_rn(fmaf(fy, 128.f, fx));   // iy*128+ix, exact
        const ulonglong2* p = Wq + ((long)idx << 3);
        u64 wx2 = pk2(wx);
        {
            ulonglong2 t00 = __ldg(p);                   // (iy  ,ix  )
            ulonglong2 t01 = __ldg(p + 8);               // (iy  ,ix+1)
            u64 v2 = pk2(1.f - wy);
            u64 s0a = f2fma(wx2, f2fma(t00.x, M1, t01.x), t00.x);
            u64 s0b = f2fma(wx2, f2fma(t00.y, M1, t01.y), t00.y);
            accA = f2fma(v2, s0a, accA);
            accB = f2fma(v2, s0b, accB);
        }
        {
            ulonglong2 t10 = __ldg(p + 1024);            // (iy+1,ix  )
            ulonglong2 t11 = __ldg(p + 1032);            // (iy+1,ix+1)
            u64 wy2 = pk2(wy);
            u64 s1a = f2fma(wx2, f2fma(t10.x, M1, t11.x), t10.x);
            u64 s1b = f2fma(wx2, f2fma(t10.y, M1, t11.y), t10.y);
            accC = f2fma(wy2, s1a, accC);
            accD = f2fma(wy2, s1b, accD);
        }
    }

    float2 Af = up2(accA), Bf = up2(accB), Cf = up2(accC), Df = up2(accD);
    const int b0 = 4 * q;
    float* o = out + (b0 * NANG + a) * RES + i;
    atomicAdd(o,                  Af.x + Cf.x);
    atomicAdd(o + NANG * RES,     Af.y + Cf.y);
    atomicAdd(o + 2 * NANG * RES, Bf.x + Df.x);
    atomicAdd(o + 3 * NANG * RES, Bf.y + Df.y);
}

// ---------------------------------------------------------------------------
// Kernel 3: masked EDGE steps (exact reference semantics: clipped indices,
// zeroed OOB taps). Block = 128 = 4 warps slicing one tile's concatenated
// masked range (head [jAw,jCw-1] + tail [jDw+1,jBw]).
// ---------------------------------------------------------------------------
__global__ __launch_bounds__(128) void k_edge(float* __restrict__ out) {
    const int lane = threadIdx.x & 31;
    const int seg  = threadIdx.x >> 5;
    const int sub  = lane >> 3;
    const int q    = lane & 7;
    const int quad = blockIdx.x;
    const int i    = quad * 4 + sub;
    const int a    = blockIdx.y;

    const int4 wn = g_win[a * 32 + quad];
    const int Lh = max(0, wn.z - wn.x);             // head length
    const int Lt = max(0, wn.y - wn.w);             // tail length
    const int L  = Lh + Lt;
    if (L <= 0) return;

    const int k0 = (seg * L) / 4;
    const int k1 = ((seg + 1) * L) / 4 - 1;
    if (k0 > k1) return;

    const float2 cs = g_trig[a];
    const float c = cs.x, s = cs.y;
    const float ci = (float)i - 63.5f;
    const float ax = fmaf(ci, c, 63.5f);
    const float ay = fmaf(ci, s, 63.5f);

    float m0 = 0.f, m1 = 0.f, m2 = 0.f, m3 = 0.f;
    const float4* W4 = (const float4*)g_W;

#pragma unroll 1
    for (int k = k0; k <= k1; k++) {
        const int j = (k < Lh) ? (wn.x + k) : (wn.w + 1 + (k - Lh));
        float cjm = (float)j - 63.5f;
        float xs = fmaf(-s, cjm, ax);
        float ys = fmaf(c, cjm, ay);
        int ix = __float2int_rd(xs), iy = __float2int_rd(ys);
        float wx = xs - (float)ix, wy = ys - (float)iy;
        float u = 1.f - wx, v = 1.f - wy;
        float mx0 = (ix >= 0 && ix < 128) ? 1.f : 0.f;
        float mx1 = (ix >= -1 && ix < 127) ? 1.f : 0.f;
        float my0 = (iy >= 0 && iy < 128) ? 1.f : 0.f;
        float my1 = (iy >= -1 && iy < 127) ? 1.f : 0.f;
        int cx0 = min(max(ix, 0), 127), cx1 = min(max(ix + 1, 0), 127);
        int cy0 = min(max(iy, 0), 127), cy1 = min(max(iy + 1, 0), 127);
        float w00 = (v * my0) * (u * mx0),  w01 = (v * my0) * (wx * mx1);
        float w10 = (wy * my1) * (u * mx0), w11 = (wy * my1) * (wx * mx1);
        float4 v00 = __ldg(&W4[(cy0 * 128 + cx0) * 8 + q]);
        float4 v01 = __ldg(&W4[(cy0 * 128 + cx1) * 8 + q]);
        float4 v10 = __ldg(&W4[(cy1 * 128 + cx0) * 8 + q]);
        float4 v11 = __ldg(&W4[(cy1 * 128 + cx1) * 8 + q]);
        m0 = fmaf(w00, v00.x, fmaf(w01, v01.x, fmaf(w10, v10.x, fmaf(w11, v11.x, m0))));
        m1 = fmaf(w00, v00.y, fmaf(w01, v01.y, fmaf(w10, v10.y, fmaf(w11, v11.y, m1))));
        m2 = fmaf(w00, v00.z, fmaf(w01, v01.z, fmaf(w10, v10.z, fmaf(w11, v11.z, m2))));
        m3 = fmaf(w00, v00.w, fmaf(w01, v01.w, fmaf(w10, v10.w, fmaf(w11, v11.w, m3))));
    }

    const int b0 = 4 * q;
    float* o = out + (b0 * NANG + a) * RES + i;
    atomicAdd(o,                  m0);
    atomicAdd(o + NANG * RES,     m1);
    atomicAdd(o + 2 * NANG * RES, m2);
    atomicAdd(o + 3 * NANG * RES, m3);
}

// ---------------------------------------------------------------------------
extern "C" void kernel_launch(void* const* d_in, const int* in_sizes, int n_in,
                              void* d_out, int out_size) {
    const float* x      = (const float*)d_in[0];   // (32,16,128,128) f32
    const float* angles = (const float*)d_in[1];   // (64,)           f32
    const float* conv_w = (const float*)d_in[2];   // (1,16,1,1)      f32
    const float* conv_b = (const float*)d_in[3];   // (1,)            f32
    float* out = (float*)d_out;                    // (32,1,64,128)   f32

    k_weight<<<RES, 1024>>>(x, conv_w, angles, conv_b, out);
    dim3 g(32, NANG);
    k_edge<<<g, 128>>>(out);
    k_fast<<<g, 128>>>(out);
}

// round 14
// speedup vs baseline: 1.2330x; 1.2330x over previous
#include <cuda_runtime.h>

#define BB   32
#define CC   16
#define RES  128
#define NANG 64

// Weighted image, batch-innermost: g_W[(y*128+x)*32 + b]
__device__ float g_W[RES * RES * BB];
// Per-angle trig and per-(angle,quad) j-windows, computed in k_weight.
__device__ float2 g_trig[NANG];
__device__ int4   g_win[NANG * 32];

// ---------------------------------------------------------------------------
// packed f32x2 helpers (sm_103a)
// ---------------------------------------------------------------------------
typedef unsigned long long u64;
__device__ __forceinline__ u64 pk2(float v) {
    u64 r; asm("mov.b64 %0,{%1,%1};" : "=l"(r) : "f"(v)); return r;
}
__device__ __forceinline__ u64 f2fma(u64 a, u64 b, u64 c) {
    u64 d; asm("fma.rn.f32x2 %0,%1,%2,%3;" : "=l"(d) : "l"(a), "l"(b), "l"(c)); return d;
}
__device__ __forceinline__ float2 up2(u64 v) {
    float2 f; asm("mov.b64 {%0,%1},%2;" : "=f"(f.x), "=f"(f.y) : "l"(v)); return f;
}

// ---------------------------------------------------------------------------
// Interval helper: intersect {j : lo < P + Q*j < hi} into [jmn, jmx].
// ---------------------------------------------------------------------------
__device__ __forceinline__ void isect(float P, float Q, float lo, float hi,
                                      float& jmn, float& jmx) {
    if (Q == 0.f) {
        if (P <= lo || P >= hi) { jmn = 1e9f; jmx = -1e9f; }
    } else {
        float t0 = (lo - P) / Q, t1 = (hi - P) / Q;
        jmn = fmaxf(jmn, fminf(t0, t1));
        jmx = fminf(jmx, fmaxf(t0, t1));
    }
}

// ---------------------------------------------------------------------------
// Kernel 1: channel-weighted image -> (y,x,b) layout; ALSO precomputes trig
// + j-windows for all (angle, row-quad) pairs in spare threads of blocks 0-63.
// ---------------------------------------------------------------------------
__global__ __launch_bounds__(1024) void k_weight(const float* __restrict__ x,
                                                 const float* __restrict__ w,
                                                 const float* __restrict__ angles) {
    __shared__ float S[RES][33];
    const int y = blockIdx.x, tid = threadIdx.x;

    // ---- window/trig precompute: warp 31 of blocks 0..63 ----
    if (y < NANG && tid >= 992) {
        const int a = y, quad = tid - 992;
        const float theta = __ldg(&angles[a]);
        const float c = cosf(theta), s = sinf(theta);
        if (quad == 0) g_trig[a] = make_float2(c, s);

        int jAw = 1 << 30, jBw = -(1 << 30), jCw = -(1 << 30), jDw = 1 << 30;
#pragma unroll 1
        for (int r = 0; r < 4; r++) {
            const int i = quad * 4 + r;
            const float ci = (float)i - 63.5f;
            const float ax = fmaf(ci, c, 63.5f);
            const float ay = fmaf(ci, s, 63.5f);
            const float A  = fmaf(63.5f, s, ax), Bq = -s;
            const float Cq = fmaf(-63.5f, c, ay), Dq = c;

            float jmn = 0.f, jmx = 127.f;
            isect(A, Bq, -1.f, 128.f, jmn, jmx);
            isect(Cq, Dq, -1.f, 128.f, jmn, jmx);
            jmn = fminf(fmaxf(jmn, 0.f), 127.f);
            jmx = fminf(fmaxf(jmx, 0.f), 127.f);
            int jA, jB;
            if (jmn > jmx) { jA = 0; jB = -1; }
            else { jA = max(0, (int)floorf(jmn) - 1); jB = min(127, (int)ceilf(jmx) + 1); }

            float jmn2 = 0.f, jmx2 = 127.f;
            isect(A, Bq, 0.01f, 126.99f, jmn2, jmx2);
            isect(Cq, Dq, 0.01f, 126.99f, jmn2, jmx2);
            jmn2 = fminf(fmaxf(jmn2, 0.f), 127.f);
            jmx2 = fminf(fmaxf(jmx2, 0.f), 127.f);
            int jC, jD;
            if (jmn2 > jmx2) { jC = jB + 1; jD = jB; }
            else {
                jC = max(jA, (int)ceilf(jmn2) + 1);
                jD = min(jB, (int)floorf(jmx2) - 1);
                if (jC > jD) { jC = jB + 1; jD = jB; }
            }
            jAw = min(jAw, jA); jBw = max(jBw, jB);
            jCw = max(jCw, jC); jDw = min(jDw, jD);
        }
        if (jDw < jCw - 1) jDw = jCw - 1;
        g_win[a * 32 + quad] = make_int4(jAw, jBw, jCw, jDw);
    }

    // ---- weighted image: thread = (batch b, 4 x-positions), float4 reads ----
    float wv[CC];
#pragma unroll
    for (int c = 0; c < CC; c++) wv[c] = __ldg(&w[c]);

    const int xi4 = tid & 31;                       // float4 index along x
    const int b   = tid >> 5;                       // batch 0..31
    const float4* px = (const float4*)(x + ((size_t)(b * CC)) * RES * RES
                                         + (size_t)y * RES) + xi4;
    float4 acc = make_float4(0.f, 0.f, 0.f, 0.f);
#pragma unroll
    for (int c = 0; c < CC; c++) {
        float4 t = __ldg(px + (size_t)c * (RES * RES / 4));
        acc.x = fmaf(wv[c], t.x, acc.x);
        acc.y = fmaf(wv[c], t.y, acc.y);
        acc.z = fmaf(wv[c], t.z, acc.z);
        acc.w = fmaf(wv[c], t.w, acc.w);
    }
    S[4 * xi4 + 0][b] = acc.x;
    S[4 * xi4 + 1][b] = acc.y;
    S[4 * xi4 + 2][b] = acc.z;
    S[4 * xi4 + 3][b] = acc.w;
    __syncthreads();

    // write phase: lanes = consecutive b -> coalesced STG.32
    const int bb = tid & 31, xg = tid >> 5;
#pragma unroll
    for (int k = 0; k < 4; k++) {
        int x2 = xg + k * 32;
        g_W[(y * 128 + x2) * 32 + bb] = S[x2][bb];
    }
}

// ---------------------------------------------------------------------------
// Kernel 2: radon. Block = 128 threads = 4 warps = 1 row-quad x 4 j-segments.
// Prologue is 2 table loads; all window math precomputed. Lanes: sub=lane>>3
// (row in quad), q=lane&7 (batch quad 4q..4q+3). Deterministic smem reduce.
// grid (32, 64); center quads scheduled first. Fast loop unrolled 8 deep for
// ~32 loads in flight per warp (latency amortization at fixed occupancy).
// ---------------------------------------------------------------------------
__global__ __launch_bounds__(128) void k_radon(const float* __restrict__ bias,
                                               float* __restrict__ out) {
    __shared__ float4 red[4][32];

    const int tid  = threadIdx.x;
    const int lane = tid & 31;
    const int seg  = tid >> 5;                      // j-segment 0..3
    const int sub  = lane >> 3;                     // row within quad
    const int q    = lane & 7;                      // batch quad: b = 4q..4q+3
    const int bx   = blockIdx.x;                    // 0..31
    const int quad = (bx & 1) ? (16 + (bx >> 1)) : (15 - (bx >> 1));
    const int i    = quad * 4 + sub;                // detector row
    const int a    = blockIdx.y;                    // angle

    const float2 cs = g_trig[a];
    const float c = cs.x, s = cs.y;
    const int4 wn = g_win[a * 32 + quad];           // jAw, jBw, jCw, jDw
    const float ci = (float)i - 63.5f;
    const float ax = fmaf(ci, c, 63.5f);
    const float ay = fmaf(ci, s, 63.5f);

    // This warp's segment of the union window [jAw, jBw]
    const int len   = wn.y - wn.x + 1;
    const int segLo = wn.x + (seg * len) / 4;
    const int segHi = wn.x + ((seg + 1) * len) / 4 - 1;
    const int jCw = wn.z, jDw = wn.w;

    u64 accA = 0, accB = 0, accC = 0, accD = 0;
    float m0 = 0.f, m1 = 0.f, m2 = 0.f, m3 = 0.f;

    const float4* W4 = (const float4*)g_W;

    // Exact masked step (reference semantics: clipped indices, zeroed OOB taps)
    auto masked = [&](int j) {
        float cjm = (float)j - 63.5f;
        float xs = fmaf(-s, cjm, ax);
        float ys = fmaf(c, cjm, ay);
        int ix = __float2int_rd(xs), iy = __float2int_rd(ys);
        float wx = xs - (float)ix, wy = ys - (float)iy;
        float u = 1.f - wx, v = 1.f - wy;
        float mx0 = (ix >= 0 && ix < 128) ? 1.f : 0.f;
        float mx1 = (ix >= -1 && ix < 127) ? 1.f : 0.f;
        float my0 = (iy >= 0 && iy < 128) ? 1.f : 0.f;
        float my1 = (iy >= -1 && iy < 127) ? 1.f : 0.f;
        int cx0 = min(max(ix, 0), 127), cx1 = min(max(ix + 1, 0), 127);
        int cy0 = min(max(iy, 0), 127), cy1 = min(max(iy + 1, 0), 127);
        float w00 = (v * my0) * (u * mx0),  w01 = (v * my0) * (wx * mx1);
        float w10 = (wy * my1) * (u * mx0), w11 = (wy * my1) * (wx * mx1);
        float4 v00 = __ldg(&W4[(cy0 * 128 + cx0) * 8 + q]);
        float4 v01 = __ldg(&W4[(cy0 * 128 + cx1) * 8 + q]);
        float4 v10 = __ldg(&W4[(cy1 * 128 + cx0) * 8 + q]);
        float4 v11 = __ldg(&W4[(cy1 * 128 + cx1) * 8 + q]);
        m0 = fmaf(w00, v00.x, fmaf(w01, v01.x, fmaf(w10, v10.x, fmaf(w11, v11.x, m0))));
        m1 = fmaf(w00, v00.y, fmaf(w01, v01.y, fmaf(w10, v10.y, fmaf(w11, v11.y, m1))));
        m2 = fmaf(w00, v00.z, fmaf(w01, v01.z, fmaf(w10, v10.z, fmaf(w11, v11.z, m2))));
        m3 = fmaf(w00, v00.w, fmaf(w01, v01.w, fmaf(w10, v10.w, fmaf(w11, v11.w, m3))));
    };

    // head (masked) | fast [jCw,jDw] | tail (masked), clipped to this segment
    const int h1 = min(segHi, jCw - 1);
#pragma unroll 1
    for (int j = segLo; j <= h1; j++) masked(j);

    const int f0 = max(segLo, jCw), f1 = min(segHi, jDw);
    if (f0 <= f1) {
        const ulonglong2* Wq = (const ulonglong2*)g_W + q;
        const u64 M1 = pk2(-1.f);
        float cj = (float)f0 - 63.5f;               // exact; += 1.0f stays exact
#pragma unroll 8
        for (int j = f0; j <= f1; j++) {
            float xs = fmaf(-s, cj, ax);
            float ys = fmaf(c, cj, ay);
            cj += 1.0f;
            float fx = floorf(xs), fy = floorf(ys);
            float wx = xs - fx,    wy = ys - fy;
            int idx = __float2int_rn(fmaf(fy, 128.f, fx));   // iy*128+ix, exact
            const ulonglong2* p = Wq + ((long)idx << 3);
            u64 wx2 = pk2(wx);
            {
                ulonglong2 t00 = __ldg(p);                   // (iy  ,ix  )
                ulonglong2 t01 = __ldg(p + 8);               // (iy  ,ix+1)
                u64 v2 = pk2(1.f - wy);
                u64 s0a = f2fma(wx2, f2fma(t00.x, M1, t01.x), t00.x);
                u64 s0b = f2fma(wx2, f2fma(t00.y, M1, t01.y), t00.y);
                accA = f2fma(v2, s0a, accA);
                accB = f2fma(v2, s0b, accB);
            }
            {
                ulonglong2 t10 = __ldg(p + 1024);            // (iy+1,ix  )
                ulonglong2 t11 = __ldg(p + 1032);            // (iy+1,ix+1)
                u64 wy2 = pk2(wy);
                u64 s1a = f2fma(wx2, f2fma(t10.x, M1, t11.x), t10.x);
                u64 s1b = f2fma(wx2, f2fma(t10.y, M1, t11.y), t10.y);
                accC = f2fma(wy2, s1a, accC);
                accD = f2fma(wy2, s1b, accD);
            }
        }
    }

    const int t0 = max(segLo, jDw + 1);
#pragma unroll 1
    for (int j = t0; j <= segHi; j++) masked(j);

    float2 Af = up2(accA), Bf = up2(accB), Cf = up2(accC), Df = up2(accD);
    float4 part;
    part.x = (Af.x + Cf.x) + m0;
    part.y = (Af.y + Cf.y) + m1;
    part.z = (Bf.x + Df.x) + m2;
    part.w = (Bf.y + Df.y) + m3;
    red[seg][lane] = part;
    __syncthreads();

    // Reduce 4 segments in fixed order (deterministic) and store.
    if (tid < 32) {
        const int qq = tid & 7, sb = tid >> 3;
        float4 r = red[0][tid];
#pragma unroll
        for (int ss = 1; ss < 4; ss++) {
            float4 p = red[ss][tid];
            r.x += p.x; r.y += p.y; r.z += p.z; r.w += p.w;
        }
        const float bv = __ldg(&bias[0]);
        const int ii = quad * 4 + sb;
        const int b0 = 4 * qq;
        out[((b0 + 0) * NANG + a) * RES + ii] = r.x + bv;
        out[((b0 + 1) * NANG + a) * RES + ii] = r.y + bv;
        out[((b0 + 2) * NANG + a) * RES + ii] = r.z + bv;
        out[((b0 + 3) * NANG + a) * RES + ii] = r.w + bv;
    }
}

// ---------------------------------------------------------------------------
extern "C" void kernel_launch(void* const* d_in, const int* in_sizes, int n_in,
                              void* d_out, int out_size) {
    const float* x      = (const float*)d_in[0];   // (32,16,128,128) f32
    const float* angles = (const float*)d_in[1];   // (64,)           f32
    const float* conv_w = (const float*)d_in[2];   // (1,16,1,1)      f32
    const float* conv_b = (const float*)d_in[3];   // (1,)            f32
    float* out = (float*)d_out;                    // (32,1,64,128)   f32

    k_weight<<<RES, 1024>>>(x, conv_w, angles);
    dim3 g(32, NANG);
    k_radon<<<g, 128>>>(conv_b, out);
}

// round 16
// speedup vs baseline: 1.3821x; 1.1209x over previous
#include <cuda_runtime.h>
#include <cuda_fp16.h>

#define BB   32
#define CC   16
#define RES  128
#define NANG 64

// Weighted image in fp16, batch-innermost: g_Wh[(y*128+x)*32 + b]
__device__ __half g_Wh[RES * RES * BB];
// Per-angle trig and per-(angle,quad) j-windows, computed in k_weight.
__device__ float2 g_trig[NANG];
__device__ int4   g_win[NANG * 32];

// ---------------------------------------------------------------------------
// packed helpers (sm_103a)
// ---------------------------------------------------------------------------
typedef unsigned long long u64;
__device__ __forceinline__ u64 pk2(float v) {
    u64 r; asm("mov.b64 %0,{%1,%1};" : "=l"(r) : "f"(v)); return r;
}
__device__ __forceinline__ u64 pkf2(float2 f) {
    u64 r; asm("mov.b64 %0,{%1,%2};" : "=l"(r) : "f"(f.x), "f"(f.y)); return r;
}
__device__ __forceinline__ u64 f2fma(u64 a, u64 b, u64 c) {
    u64 d; asm("fma.rn.f32x2 %0,%1,%2,%3;" : "=l"(d) : "l"(a), "l"(b), "l"(c)); return d;
}
__device__ __forceinline__ float2 up2(u64 v) {
    float2 f; asm("mov.b64 {%0,%1},%2;" : "=f"(f.x), "=f"(f.y) : "l"(v)); return f;
}
// uint2 (4 halves) -> float4
__device__ __forceinline__ float4 h4(uint2 u) {
    __half2 lo = *reinterpret_cast<__half2*>(&u.x);
    __half2 hi = *reinterpret_cast<__half2*>(&u.y);
    float2 a = __half22float2(lo), b = __half22float2(hi);
    return make_float4(a.x, a.y, b.x, b.y);
}

// ---------------------------------------------------------------------------
// Interval helper: intersect {j : lo < P + Q*j < hi} into [jmn, jmx].
// ---------------------------------------------------------------------------
__device__ __forceinline__ void isect(float P, float Q, float lo, float hi,
                                      float& jmn, float& jmx) {
    if (Q == 0.f) {
        if (P <= lo || P >= hi) { jmn = 1e9f; jmx = -1e9f; }
    } else {
        float t0 = (lo - P) / Q, t1 = (hi - P) / Q;
        jmn = fmaxf(jmn, fminf(t0, t1));
        jmx = fminf(jmx, fmaxf(t0, t1));
    }
}

// ---------------------------------------------------------------------------
// Kernel 1: channel-weighted image -> fp16 (y,x,b) layout; windows+trig in
// spare warp of blocks 0..63.
// ---------------------------------------------------------------------------
__global__ __launch_bounds__(1024) void k_weight(const float* __restrict__ x,
                                                 const float* __restrict__ w,
                                                 const float* __restrict__ angles) {
    __shared__ float S[RES][33];
    const int y = blockIdx.x, tid = threadIdx.x;

    // ---- window/trig precompute: warp 31 of blocks 0..63 ----
    if (y < NANG && tid >= 992) {
        const int a = y, quad = tid - 992;
        const float theta = __ldg(&angles[a]);
        const float c = cosf(theta), s = sinf(theta);
        if (quad == 0) g_trig[a] = make_float2(c, s);

        int jAw = 1 << 30, jBw = -(1 << 30), jCw = -(1 << 30), jDw = 1 << 30;
#pragma unroll 1
        for (int r = 0; r < 4; r++) {
            const int i = quad * 4 + r;
            const float ci = (float)i - 63.5f;
            const float ax = fmaf(ci, c, 63.5f);
            const float ay = fmaf(ci, s, 63.5f);
            const float A  = fmaf(63.5f, s, ax), Bq = -s;
            const float Cq = fmaf(-63.5f, c, ay), Dq = c;

            float jmn = 0.f, jmx = 127.f;
            isect(A, Bq, -1.f, 128.f, jmn, jmx);
            isect(Cq, Dq, -1.f, 128.f, jmn, jmx);
            jmn = fminf(fmaxf(jmn, 0.f), 127.f);
            jmx = fminf(fmaxf(jmx, 0.f), 127.f);
            int jA, jB;
            if (jmn > jmx) { jA = 0; jB = -1; }
            else { jA = max(0, (int)floorf(jmn) - 1); jB = min(127, (int)ceilf(jmx) + 1); }

            float jmn2 = 0.f, jmx2 = 127.f;
            isect(A, Bq, 0.01f, 126.99f, jmn2, jmx2);
            isect(Cq, Dq, 0.01f, 126.99f, jmn2, jmx2);
            jmn2 = fminf(fmaxf(jmn2, 0.f), 127.f);
            jmx2 = fminf(fmaxf(jmx2, 0.f), 127.f);
            int jC, jD;
            if (jmn2 > jmx2) { jC = jB + 1; jD = jB; }
            else {
                jC = max(jA, (int)ceilf(jmn2) + 1);
                jD = min(jB, (int)floorf(jmx2) - 1);
                if (jC > jD) { jC = jB + 1; jD = jB; }
            }
            jAw = min(jAw, jA); jBw = max(jBw, jB);
            jCw = max(jCw, jC); jDw = min(jDw, jD);
        }
        if (jDw < jCw - 1) jDw = jCw - 1;
        g_win[a * 32 + quad] = make_int4(jAw, jBw, jCw, jDw);
    }

    // ---- weighted image: thread = (batch b, 4 x-positions), float4 reads ----
    float wv[CC];
#pragma unroll
    for (int c = 0; c < CC; c++) wv[c] = __ldg(&w[c]);

    const int xi4 = tid & 31;                       // float4 index along x
    const int b   = tid >> 5;                       // batch 0..31
    const float4* px = (const float4*)(x + ((size_t)(b * CC)) * RES * RES
                                         + (size_t)y * RES) + xi4;
    float4 acc = make_float4(0.f, 0.f, 0.f, 0.f);
#pragma unroll
    for (int c = 0; c < CC; c++) {
        float4 t = __ldg(px + (size_t)c * (RES * RES / 4));
        acc.x = fmaf(wv[c], t.x, acc.x);
        acc.y = fmaf(wv[c], t.y, acc.y);
        acc.z = fmaf(wv[c], t.z, acc.z);
        acc.w = fmaf(wv[c], t.w, acc.w);
    }
    S[4 * xi4 + 0][b] = acc.x;
    S[4 * xi4 + 1][b] = acc.y;
    S[4 * xi4 + 2][b] = acc.z;
    S[4 * xi4 + 3][b] = acc.w;
    __syncthreads();

    // write phase: lanes = consecutive b -> coalesced half stores
    const int bb = tid & 31, xg = tid >> 5;
#pragma unroll
    for (int k = 0; k < 4; k++) {
        int x2 = xg + k * 32;
        g_Wh[(y * 128 + x2) * 32 + bb] = __float2half_rn(S[x2][bb]);
    }
}

// ---------------------------------------------------------------------------
// Kernel 2: radon. Block = 128 threads = 4 warps = 1 row-quad x 4 j-segments.
// Lanes: sub=lane>>3 (row in quad), q=lane&7 (batch quad 4q..4q+3).
// Fast loop: 4 batched LDG.64 (fp16 taps, MLP>=4/step), HFMA2 x-lerp,
// fp32 y-combine + accumulate. Deterministic smem reduce. grid (32, 64).
// ---------------------------------------------------------------------------
__global__ __launch_bounds__(128) void k_radon(const float* __restrict__ bias,
                                               float* __restrict__ out) {
    __shared__ float4 red[4][32];

    const int tid  = threadIdx.x;
    const int lane = tid & 31;
    const int seg  = tid >> 5;                      // j-segment 0..3
    const int sub  = lane >> 3;                     // row within quad
    const int q    = lane & 7;                      // batch quad: b = 4q..4q+3
    const int bx   = blockIdx.x;                    // 0..31
    const int quad = (bx & 1) ? (16 + (bx >> 1)) : (15 - (bx >> 1));
    const int i    = quad * 4 + sub;                // detector row
    const int a    = blockIdx.y;                    // angle

    const float2 cs = g_trig[a];
    const float c = cs.x, s = cs.y;
    const int4 wn = g_win[a * 32 + quad];           // jAw, jBw, jCw, jDw
    const float ci = (float)i - 63.5f;
    const float ax = fmaf(ci, c, 63.5f);
    const float ay = fmaf(ci, s, 63.5f);

    // This warp's segment of the union window [jAw, jBw]
    const int len   = wn.y - wn.x + 1;
    const int segLo = wn.x + (seg * len) / 4;
    const int segHi = wn.x + ((seg + 1) * len) / 4 - 1;
    const int jCw = wn.z, jDw = wn.w;

    u64 accA = 0, accB = 0, accC = 0, accD = 0;
    float m0 = 0.f, m1 = 0.f, m2 = 0.f, m3 = 0.f;

    const uint2* W2 = (const uint2*)g_Wh;           // uint2 = 4 halves = 1 batch quad

    // Exact masked step (reference semantics: clipped indices, zeroed OOB taps)
    auto masked = [&](int j) {
        float cjm = (float)j - 63.5f;
        float xs = fmaf(-s, cjm, ax);
        float ys = fmaf(c, cjm, ay);
        int ix = __float2int_rd(xs), iy = __float2int_rd(ys);
        float wx = xs - (float)ix, wy = ys - (float)iy;
        float u = 1.f - wx, v = 1.f - wy;
        float mx0 = (ix >= 0 && ix < 128) ? 1.f : 0.f;
        float mx1 = (ix >= -1 && ix < 127) ? 1.f : 0.f;
        float my0 = (iy >= 0 && iy < 128) ? 1.f : 0.f;
        float my1 = (iy >= -1 && iy < 127) ? 1.f : 0.f;
        int cx0 = min(max(ix, 0), 127), cx1 = min(max(ix + 1, 0), 127);
        int cy0 = min(max(iy, 0), 127), cy1 = min(max(iy + 1, 0), 127);
        float w00 = (v * my0) * (u * mx0),  w01 = (v * my0) * (wx * mx1);
        float w10 = (wy * my1) * (u * mx0), w11 = (wy * my1) * (wx * mx1);
        uint2 r00 = __ldg(&W2[(cy0 * 128 + cx0) * 8 + q]);
        uint2 r01 = __ldg(&W2[(cy0 * 128 + cx1) * 8 + q]);
        uint2 r10 = __ldg(&W2[(cy1 * 128 + cx0) * 8 + q]);
        uint2 r11 = __ldg(&W2[(cy1 * 128 + cx1) * 8 + q]);
        float4 v00 = h4(r00), v01 = h4(r01), v10 = h4(r10), v11 = h4(r11);
        m0 = fmaf(w00, v00.x, fmaf(w01, v01.x, fmaf(w10, v10.x, fmaf(w11, v11.x, m0))));
        m1 = fmaf(w00, v00.y, fmaf(w01, v01.y, fmaf(w10, v10.y, fmaf(w11, v11.y, m1))));
        m2 = fmaf(w00, v00.z, fmaf(w01, v01.z, fmaf(w10, v10.z, fmaf(w11, v11.z, m2))));
        m3 = fmaf(w00, v00.w, fmaf(w01, v01.w, fmaf(w10, v10.w, fmaf(w11, v11.w, m3))));
    };

    // head (masked) | fast [jCw,jDw] | tail (masked), clipped to this segment
    const int h1 = min(segHi, jCw - 1);
#pragma unroll 1
    for (int j = segLo; j <= h1; j++) masked(j);

    const int f0 = max(segLo, jCw), f1 = min(segHi, jDw);
    if (f0 <= f1) {
        const uint2* Wq = W2 + q;                   // batch-quad base
        float cj = (float)f0 - 63.5f;               // exact; += 1.0f stays exact
#pragma unroll 4
        for (int j = f0; j <= f1; j++) {
            float xs = fmaf(-s, cj, ax);
            float ys = fmaf(c, cj, ay);
            cj += 1.0f;
            float fx = floorf(xs), fy = floorf(ys);
            float wx = xs - fx,    wy = ys - fy;
            int idx = __float2int_rn(fmaf(fy, 128.f, fx));   // iy*128+ix, exact
            const uint2* p = Wq + ((long)idx << 3);
            // ALL four tap loads issued before any consumer (MLP >= 4/step)
            uint2 t00 = __ldg(p);                    // (iy  ,ix  ) batches 4q..4q+3
            uint2 t01 = __ldg(p + 8);                // (iy  ,ix+1)
            uint2 t10 = __ldg(p + 1024);             // (iy+1,ix  )
            uint2 t11 = __ldg(p + 1032);             // (iy+1,ix+1)
            // fp16 x-lerp: s = t0 + wx*(t1 - t0)
            __half2 wxh = __float2half2_rn(wx);
            __half2 a00 = *reinterpret_cast<__half2*>(&t00.x);
            __half2 b00 = *reinterpret_cast<__half2*>(&t00.y);
            __half2 a01 = *reinterpret_cast<__half2*>(&t01.x);
            __half2 b01 = *reinterpret_cast<__half2*>(&t01.y);
            __half2 a10 = *reinterpret_cast<__half2*>(&t10.x);
            __half2 b10 = *reinterpret_cast<__half2*>(&t10.y);
            __half2 a11 = *reinterpret_cast<__half2*>(&t11.x);
            __half2 b11 = *reinterpret_cast<__half2*>(&t11.y);
            __half2 s0a = __hfma2(wxh, __hsub2(a01, a00), a00);
            __half2 s0b = __hfma2(wxh, __hsub2(b01, b00), b00);
            __half2 s1a = __hfma2(wxh, __hsub2(a11, a10), a10);
            __half2 s1b = __hfma2(wxh, __hsub2(b11, b10), b10);
            // fp32 y-combine + accumulate (packed f32x2)
            u64 v2 = pk2(1.f - wy), wy2 = pk2(wy);
            accA = f2fma(v2,  pkf2(__half22float2(s0a)), accA);
            accB = f2fma(v2,  pkf2(__half22float2(s0b)), accB);
            accC = f2fma(wy2, pkf2(__half22float2(s1a)), accC);
            accD = f2fma(wy2, pkf2(__half22float2(s1b)), accD);
        }
    }

    const int t0 = max(segLo, jDw + 1);
#pragma unroll 1
    for (int j = t0; j <= segHi; j++) masked(j);

    float2 Af = up2(accA), Bf = up2(accB), Cf = up2(accC), Df = up2(accD);
    float4 part;
    part.x = (Af.x + Cf.x) + m0;
    part.y = (Af.y + Cf.y) + m1;
    part.z = (Bf.x + Df.x) + m2;
    part.w = (Bf.y + Df.y) + m3;
    red[seg][lane] = part;
    __syncthreads();

    // Reduce 4 segments in fixed order (deterministic) and store.
    if (tid < 32) {
        const int qq = tid & 7, sb = tid >> 3;
        float4 r = red[0][tid];
#pragma unroll
        for (int ss = 1; ss < 4; ss++) {
            float4 p = red[ss][tid];
            r.x += p.x; r.y += p.y; r.z += p.z; r.w += p.w;
        }
        const float bv = __ldg(&bias[0]);
        const int ii = quad * 4 + sb;
        const int b0 = 4 * qq;
        out[((b0 + 0) * NANG + a) * RES + ii] = r.x + bv;
        out[((b0 + 1) * NANG + a) * RES + ii] = r.y + bv;
        out[((b0 + 2) * NANG + a) * RES + ii] = r.z + bv;
        out[((b0 + 3) * NANG + a) * RES + ii] = r.w + bv;
    }
}

// ---------------------------------------------------------------------------
extern "C" void kernel_launch(void* const* d_in, const int* in_sizes, int n_in,
                              void* d_out, int out_size) {
    const float* x      = (const float*)d_in[0];   // (32,16,128,128) f32
    const float* angles = (const float*)d_in[1];   // (64,)           f32
    const float* conv_w = (const float*)d_in[2];   // (1,16,1,1)      f32
    const float* conv_b = (const float*)d_in[3];   // (1,)            f32
    float* out = (float*)d_out;                    // (32,1,64,128)   f32

    k_weight<<<RES, 1024>>>(x, conv_w, angles);
    dim3 g(32, NANG);
    k_radon<<<g, 128>>>(conv_b, out);
}

// round 17
// speedup vs baseline: 1.7369x; 1.2567x over previous
#include <cuda_runtime.h>
#include <cuda_fp16.h>

#define BB   32
#define CC   16
#define RES  128
#define NANG 64

// Weighted image in fp16, batch-innermost: g_Wh[(y*128+x)*32 + b]
__device__ __half g_Wh[RES * RES * BB];
// Per-angle trig and per-(angle,quad) j-windows, computed in k_weight.
__device__ float2 g_trig[NANG];
__device__ int4   g_win[NANG * 32];

// ---------------------------------------------------------------------------
// packed helpers (sm_103a)
// ---------------------------------------------------------------------------
typedef unsigned long long u64;
__device__ __forceinline__ u64 pkf2(float2 f) {
    u64 r; asm("mov.b64 %0,{%1,%2};" : "=l"(r) : "f"(f.x), "f"(f.y)); return r;
}
__device__ __forceinline__ u64 f2add(u64 a, u64 b) {
    u64 d; asm("add.rn.f32x2 %0,%1,%2;" : "=l"(d) : "l"(a), "l"(b)); return d;
}
__device__ __forceinline__ float2 up2(u64 v) {
    float2 f; asm("mov.b64 {%0,%1},%2;" : "=f"(f.x), "=f"(f.y) : "l"(v)); return f;
}
// uint2 (4 halves) -> float4
__device__ __forceinline__ float4 h4(uint2 u) {
    __half2 lo = *reinterpret_cast<__half2*>(&u.x);
    __half2 hi = *reinterpret_cast<__half2*>(&u.y);
    float2 a = __half22float2(lo), b = __half22float2(hi);
    return make_float4(a.x, a.y, b.x, b.y);
}

// ---------------------------------------------------------------------------
// Interval helper: intersect {j : lo < P + Q*j < hi} into [jmn, jmx].
// ---------------------------------------------------------------------------
__device__ __forceinline__ void isect(float P, float Q, float lo, float hi,
                                      float& jmn, float& jmx) {
    if (Q == 0.f) {
        if (P <= lo || P >= hi) { jmn = 1e9f; jmx = -1e9f; }
    } else {
        float t0 = (lo - P) / Q, t1 = (hi - P) / Q;
        jmn = fmaxf(jmn, fminf(t0, t1));
        jmx = fminf(jmx, fmaxf(t0, t1));
    }
}

// ---------------------------------------------------------------------------
// Kernel 1: channel-weighted image -> fp16 (y,x,b) layout; windows+trig in
// spare warp of blocks 0..63; bias-initializes out (k_radon accumulates).
// ---------------------------------------------------------------------------
__global__ __launch_bounds__(1024) void k_weight(const float* __restrict__ x,
                                                 const float* __restrict__ w,
                                                 const float* __restrict__ angles,
                                                 const float* __restrict__ bias,
                                                 float* __restrict__ out) {
    __shared__ float S[RES][33];
    const int y = blockIdx.x, tid = threadIdx.x;

    // ---- bias init of out (262144 elems; 128 blocks x 1024 x 2) ----
    {
        const float bv = __ldg(&bias[0]);
        const int g0 = y * 1024 + tid;
        out[g0] = bv;
        out[g0 + 131072] = bv;
    }

    // ---- window/trig precompute: warp 31 of blocks 0..63 ----
    if (y < NANG && tid >= 992) {
        const int a = y, quad = tid - 992;
        const float theta = __ldg(&angles[a]);
        const float c = cosf(theta), s = sinf(theta);
        if (quad == 0) g_trig[a] = make_float2(c, s);

        int jAw = 1 << 30, jBw = -(1 << 30), jCw = -(1 << 30), jDw = 1 << 30;
#pragma unroll 1
        for (int r = 0; r < 4; r++) {
            const int i = quad * 4 + r;
            const float ci = (float)i - 63.5f;
            const float ax = fmaf(ci, c, 63.5f);
            const float ay = fmaf(ci, s, 63.5f);
            const float A  = fmaf(63.5f, s, ax), Bq = -s;
            const float Cq = fmaf(-63.5f, c, ay), Dq = c;

            float jmn = 0.f, jmx = 127.f;
            isect(A, Bq, -1.f, 128.f, jmn, jmx);
            isect(Cq, Dq, -1.f, 128.f, jmn, jmx);
            jmn = fminf(fmaxf(jmn, 0.f), 127.f);
            jmx = fminf(fmaxf(jmx, 0.f), 127.f);
            int jA, jB;
            if (jmn > jmx) { jA = 0; jB = -1; }
            else { jA = max(0, (int)floorf(jmn) - 1); jB = min(127, (int)ceilf(jmx) + 1); }

            float jmn2 = 0.f, jmx2 = 127.f;
            isect(A, Bq, 0.01f, 126.99f, jmn2, jmx2);
            isect(Cq, Dq, 0.01f, 126.99f, jmn2, jmx2);
            jmn2 = fminf(fmaxf(jmn2, 0.f), 127.f);
            jmx2 = fminf(fmaxf(jmx2, 0.f), 127.f);
            int jC, jD;
            if (jmn2 > jmx2) { jC = jB + 1; jD = jB; }
            else {
                jC = max(jA, (int)ceilf(jmn2) + 1);
                jD = min(jB, (int)floorf(jmx2) - 1);
                if (jC > jD) { jC = jB + 1; jD = jB; }
            }
            jAw = min(jAw, jA); jBw = max(jBw, jB);
            jCw = max(jCw, jC); jDw = min(jDw, jD);
        }
        if (jDw < jCw - 1) jDw = jCw - 1;
        g_win[a * 32 + quad] = make_int4(jAw, jBw, jCw, jDw);
    }

    // ---- weighted image: thread = (batch b, 4 x-positions), float4 reads ----
    float wv[CC];
#pragma unroll
    for (int c = 0; c < CC; c++) wv[c] = __ldg(&w[c]);

    const int xi4 = tid & 31;                       // float4 index along x
    const int b   = tid >> 5;                       // batch 0..31
    const float4* px = (const float4*)(x + ((size_t)(b * CC)) * RES * RES
                                         + (size_t)y * RES) + xi4;
    float4 acc = make_float4(0.f, 0.f, 0.f, 0.f);
#pragma unroll
    for (int c = 0; c < CC; c++) {
        float4 t = __ldg(px + (size_t)c * (RES * RES / 4));
        acc.x = fmaf(wv[c], t.x, acc.x);
        acc.y = fmaf(wv[c], t.y, acc.y);
        acc.z = fmaf(wv[c], t.z, acc.z);
        acc.w = fmaf(wv[c], t.w, acc.w);
    }
    S[4 * xi4 + 0][b] = acc.x;
    S[4 * xi4 + 1][b] = acc.y;
    S[4 * xi4 + 2][b] = acc.z;
    S[4 * xi4 + 3][b] = acc.w;
    __syncthreads();

    // write phase: lanes = consecutive b -> coalesced half stores
    const int bb = tid & 31, xg = tid >> 5;
#pragma unroll
    for (int k = 0; k < 4; k++) {
        int x2 = xg + k * 32;
        g_Wh[(y * 128 + x2) * 32 + bb] = __float2half_rn(S[x2][bb]);
    }
}

// ---------------------------------------------------------------------------
// Kernel 2: radon. grid (64, 64): bx = (quad, half-window); block = 128
// threads = 4 warps = 4 of the window's 8 segments. Lanes: sub=lane>>3 (row
// in quad), q=lane&7 (batch quad 4q..4q+3). Fast loop: 4 batched LDG.64,
// HFMA2 x-lerp AND y-lerp, fp32 accumulate (f32x2 add). Per-block partials
// flushed with atomicAdd into bias-pre-initialized out.
// ---------------------------------------------------------------------------
__global__ __launch_bounds__(128) void k_radon(float* __restrict__ out) {
    __shared__ float4 red[4][32];

    const int tid  = threadIdx.x;
    const int lane = tid & 31;
    const int sub  = lane >> 3;                     // row within quad
    const int q    = lane & 7;                      // batch quad: b = 4q..4q+3
    const int bx   = blockIdx.x;                    // 0..63
    const int q2   = bx >> 1;                       // 0..31
    const int half = bx & 1;
    const int quad = (q2 & 1) ? (16 + (q2 >> 1)) : (15 - (q2 >> 1));
    const int seg8 = half * 4 + (tid >> 5);         // segment 0..7 of window
    const int i    = quad * 4 + sub;                // detector row
    const int a    = blockIdx.y;                    // angle

    const float2 cs = g_trig[a];
    const float c = cs.x, s = cs.y;
    const int4 wn = g_win[a * 32 + quad];           // jAw, jBw, jCw, jDw
    const float ci = (float)i - 63.5f;
    const float ax = fmaf(ci, c, 63.5f);
    const float ay = fmaf(ci, s, 63.5f);

    // This warp's 1/8 segment of the union window [jAw, jBw]
    const int len   = wn.y - wn.x + 1;
    const int segLo = wn.x + (seg8 * len) / 8;
    const int segHi = wn.x + ((seg8 + 1) * len) / 8 - 1;
    const int jCw = wn.z, jDw = wn.w;

    u64 accA = 0, accB = 0;                         // batches (4q,4q+1),(4q+2,4q+3)
    float m0 = 0.f, m1 = 0.f, m2 = 0.f, m3 = 0.f;

    const uint2* W2 = (const uint2*)g_Wh;

    // Exact masked step (reference semantics: clipped indices, zeroed OOB taps)
    auto masked = [&](int j) {
        float cjm = (float)j - 63.5f;
        float xs = fmaf(-s, cjm, ax);
        float ys = fmaf(c, cjm, ay);
        int ix = __float2int_rd(xs), iy = __float2int_rd(ys);
        float wx = xs - (float)ix, wy = ys - (float)iy;
        float u = 1.f - wx, v = 1.f - wy;
        float mx0 = (ix >= 0 && ix < 128) ? 1.f : 0.f;
        float mx1 = (ix >= -1 && ix < 127) ? 1.f : 0.f;
        float my0 = (iy >= 0 && iy < 128) ? 1.f : 0.f;
        float my1 = (iy >= -1 && iy < 127) ? 1.f : 0.f;
        int cx0 = min(max(ix, 0), 127), cx1 = min(max(ix + 1, 0), 127);
        int cy0 = min(max(iy, 0), 127), cy1 = min(max(iy + 1, 0), 127);
        float w00 = (v * my0) * (u * mx0),  w01 = (v * my0) * (wx * mx1);
        float w10 = (wy * my1) * (u * mx0), w11 = (wy * my1) * (wx * mx1);
        uint2 r00 = __ldg(&W2[(cy0 * 128 + cx0) * 8 + q]);
        uint2 r01 = __ldg(&W2[(cy0 * 128 + cx1) * 8 + q]);
        uint2 r10 = __ldg(&W2[(cy1 * 128 + cx0) * 8 + q]);
        uint2 r11 = __ldg(&W2[(cy1 * 128 + cx1) * 8 + q]);
        float4 v00 = h4(r00), v01 = h4(r01), v10 = h4(r10), v11 = h4(r11);
        m0 = fmaf(w00, v00.x, fmaf(w01, v01.x, fmaf(w10, v10.x, fmaf(w11, v11.x, m0))));
        m1 = fmaf(w00, v00.y, fmaf(w01, v01.y, fmaf(w10, v10.y, fmaf(w11, v11.y, m1))));
        m2 = fmaf(w00, v00.z, fmaf(w01, v01.z, fmaf(w10, v10.z, fmaf(w11, v11.z, m2))));
        m3 = fmaf(w00, v00.w, fmaf(w01, v01.w, fmaf(w10, v10.w, fmaf(w11, v11.w, m3))));
    };

    // head (masked) | fast [jCw,jDw] | tail (masked), clipped to this segment
    const int h1 = min(segHi, jCw - 1);
#pragma unroll 1
    for (int j = segLo; j <= h1; j++) masked(j);

    const int f0 = max(segLo, jCw), f1 = min(segHi, jDw);
    if (f0 <= f1) {
        const uint2* Wq = W2 + q;                   // batch-quad base
        float cj = (float)f0 - 63.5f;               // exact; += 1.0f stays exact
#pragma unroll 4
        for (int j = f0; j <= f1; j++) {
            float xs = fmaf(-s, cj, ax);
            float ys = fmaf(c, cj, ay);
            cj += 1.0f;
            float fx = floorf(xs), fy = floorf(ys);
            float wx = xs - fx,    wy = ys - fy;
            int idx = __float2int_rn(fmaf(fy, 128.f, fx));   // iy*128+ix, exact
            const uint2* p = Wq + ((long)idx << 3);
            // ALL four tap loads issued before any consumer (MLP >= 4/step)
            uint2 t00 = __ldg(p);                    // (iy  ,ix  ) batches 4q..4q+3
            uint2 t01 = __ldg(p + 8);                // (iy  ,ix+1)
            uint2 t10 = __ldg(p + 1024);             // (iy+1,ix  )
            uint2 t11 = __ldg(p + 1032);             // (iy+1,ix+1)
            __half2 wxh = __float2half2_rn(wx);
            __half2 wyh = __float2half2_rn(wy);
            __half2 a00 = *reinterpret_cast<__half2*>(&t00.x);
            __half2 b00 = *reinterpret_cast<__half2*>(&t00.y);
            __half2 a01 = *reinterpret_cast<__half2*>(&t01.x);
            __half2 b01 = *reinterpret_cast<__half2*>(&t01.y);
            __half2 a10 = *reinterpret_cast<__half2*>(&t10.x);
            __half2 b10 = *reinterpret_cast<__half2*>(&t10.y);
            __half2 a11 = *reinterpret_cast<__half2*>(&t11.x);
            __half2 b11 = *reinterpret_cast<__half2*>(&t11.y);
            // x-lerp (fp16): s = t0 + wx*(t1 - t0)
            __half2 s0a = __hfma2(wxh, __hsub2(a01, a00), a00);
            __half2 s0b = __hfma2(wxh, __hsub2(b01, b00), b00);
            __half2 s1a = __hfma2(wxh, __hsub2(a11, a10), a10);
            __half2 s1b = __hfma2(wxh, __hsub2(b11, b10), b10);
            // y-lerp (fp16): r = s0 + wy*(s1 - s0)
            __half2 ra = __hfma2(wyh, __hsub2(s1a, s0a), s0a);
            __half2 rb = __hfma2(wyh, __hsub2(s1b, s0b), s0b);
            // fp32 accumulate (packed f32x2 add)
            accA = f2add(accA, pkf2(__half22float2(ra)));
            accB = f2add(accB, pkf2(__half22float2(rb)));
        }
    }

    const int t0 = max(segLo, jDw + 1);
#pragma unroll 1
    for (int j = t0; j <= segHi; j++) masked(j);

    float2 Af = up2(accA), Bf = up2(accB);
    float4 part;
    part.x = Af.x + m0;
    part.y = Af.y + m1;
    part.z = Bf.x + m2;
    part.w = Bf.y + m3;
    red[tid >> 5][lane] = part;
    __syncthreads();

    // Reduce 4 warps in fixed order; flush block partial via atomicAdd.
    if (tid < 32) {
        const int qq = tid & 7, sb = tid >> 3;
        float4 r = red[0][tid];
#pragma unroll
        for (int ss = 1; ss < 4; ss++) {
            float4 p = red[ss][tid];
            r.x += p.x; r.y += p.y; r.z += p.z; r.w += p.w;
        }
        const int ii = quad * 4 + sb;
        const int b0 = 4 * qq;
        float* o = out + (b0 * NANG + a) * RES + ii;
        atomicAdd(o,                  r.x);
        atomicAdd(o + NANG * RES,     r.y);
        atomicAdd(o + 2 * NANG * RES, r.z);
        atomicAdd(o + 3 * NANG * RES, r.w);
    }
}

// ---------------------------------------------------------------------------
extern "C" void kernel_launch(void* const* d_in, const int* in_sizes, int n_in,
                              void* d_out, int out_size) {
    const float* x      = (const float*)d_in[0];   // (32,16,128,128) f32
    const float* angles = (const float*)d_in[1];   // (64,)           f32
    const float* conv_w = (const float*)d_in[2];   // (1,16,1,1)      f32
    const float* conv_b = (const float*)d_in[3];   // (1,)            f32
    float* out = (float*)d_out;                    // (32,1,64,128)   f32

    k_weight<<<RES, 1024>>>(x, conv_w, angles, conv_b, out);
    dim3 g(64, NANG);
    k_radon<<<g, 128>>>(out);
}